// round 14
// baseline (speedup 1.0000x reference)
#include <cuda_runtime.h>
#include <cuda_bf16.h>
#include <cstdint>

#define DD 128
#define NMAX 50000
#define EMAX 600000
#define GMAX 64

// ---------------- scratch (no allocations allowed) ----------------
__device__ float g_x1[NMAX * DD];          // fp32 layer outputs (ping-pong)
__device__ float g_x2[NMAX * DD];
__device__ __nv_bfloat16 g_xa_h[NMAX * DD];   // gather out (bf16 hi/lo)
__device__ __nv_bfloat16 g_xa_l[NMAX * DD];
__device__ __nv_bfloat16 g_h_h[NMAX * DD];    // GEMM1 out
__device__ __nv_bfloat16 g_h_l[NMAX * DD];
__device__ __nv_bfloat16 g_xsA_h[NMAX * DD];  // split of layer input (ping-pong)
__device__ __nv_bfloat16 g_xsA_l[NMAX * DD];
__device__ __nv_bfloat16 g_xsB_h[NMAX * DD];
__device__ __nv_bfloat16 g_xsB_l[NMAX * DD];
__device__ float g_sums[GMAX * DD];
__device__ float g_counts[GMAX];
__device__ __nv_bfloat16 g_wT1_hi[3 * DD * DD];
__device__ __nv_bfloat16 g_wT1_lo[3 * DD * DD];
__device__ __nv_bfloat16 g_wTc_hi[3 * DD * 256];
__device__ __nv_bfloat16 g_wTc_lo[3 * DD * 256];
__device__ float g_bc[3 * DD];
__device__ int g_deg[NMAX];
__device__ int g_rowptr[NMAX + 1];
__device__ int g_cursor[NMAX];
__device__ int g_adj[EMAX];
__device__ int g_bsum[128];

// ---------------- helpers ----------------
__device__ __forceinline__ uint32_t smem_u32(const void* p) {
    uint32_t a;
    asm("{ .reg .u64 t; cvta.to.shared.u64 t, %1; cvt.u32.u64 %0, t; }"
        : "=r"(a) : "l"(p));
    return a;
}
__device__ __forceinline__ uint32_t packbf(float a, float b) {
    __nv_bfloat162 t = __floats2bfloat162_rn(a, b);
    return *reinterpret_cast<uint32_t*>(&t);
}
__device__ __forceinline__ float bfhi(float v) {
    return __bfloat162float(__float2bfloat16_rn(v));
}
__device__ __forceinline__ void ldm4(uint32_t& r0, uint32_t& r1, uint32_t& r2,
                                     uint32_t& r3, uint32_t addr) {
    asm volatile("ldmatrix.sync.aligned.m8n8.x4.shared.b16 {%0,%1,%2,%3}, [%4];"
                 : "=r"(r0), "=r"(r1), "=r"(r2), "=r"(r3) : "r"(addr));
}
__device__ __forceinline__ void mma16816(float* c, const uint32_t* a, const uint32_t* b) {
    asm volatile(
        "mma.sync.aligned.m16n8k16.row.col.f32.bf16.bf16.f32 "
        "{%0,%1,%2,%3}, {%4,%5,%6,%7}, {%8,%9}, {%0,%1,%2,%3};"
        : "+f"(c[0]), "+f"(c[1]), "+f"(c[2]), "+f"(c[3])
        : "r"(a[0]), "r"(a[1]), "r"(a[2]), "r"(a[3]), "r"(b[0]), "r"(b[1]));
}
__device__ __forceinline__ void cp16(uint32_t saddr, const void* g) {
    asm volatile("cp.async.ca.shared.global [%0], [%1], 16;" :: "r"(saddr), "l"(g));
}
// src-size variant: full=16 copies, full=0 zero-fills the 16 smem bytes
__device__ __forceinline__ void cp16z(uint32_t saddr, const void* g, int full) {
    asm volatile("cp.async.ca.shared.global [%0], [%1], 16, %2;"
                 :: "r"(saddr), "l"(g), "r"(full));
}
#define CP_COMMIT() asm volatile("cp.async.commit_group;" ::: "memory")
#define CP_WAIT0() asm volatile("cp.async.wait_group 0;" ::: "memory")

// ---------------- CSR build ----------------
__global__ void deg_kernel(const int* __restrict__ ei, int* __restrict__ deg, int E) {
    int e = blockIdx.x * blockDim.x + threadIdx.x;
    if (e < E) atomicAdd(&deg[ei[E + e]], 1);
}
__global__ void scan1(const int* __restrict__ deg, int* __restrict__ rowptr,
                      int* __restrict__ bsum, int N) {
    __shared__ int ws[16];
    int i = blockIdx.x * 512 + threadIdx.x;
    int lane = threadIdx.x & 31, w = threadIdx.x >> 5;
    int v = (i < N) ? deg[i] : 0;
#pragma unroll
    for (int o = 1; o < 32; o <<= 1) {
        int t = __shfl_up_sync(0xFFFFFFFFu, v, o);
        if (lane >= o) v += t;
    }
    if (lane == 31) ws[w] = v;
    __syncthreads();
    if (w == 0) {
        int s = (lane < 16) ? ws[lane] : 0;
#pragma unroll
        for (int o = 1; o < 16; o <<= 1) {
            int t = __shfl_up_sync(0xFFFFFFFFu, s, o);
            if (lane >= o) s += t;
        }
        if (lane < 16) ws[lane] = s;
    }
    __syncthreads();
    if (w > 0) v += ws[w - 1];
    if (i < N) rowptr[i + 1] = v;
    if (threadIdx.x == 511) bsum[blockIdx.x] = v;
}
__global__ void scan2(int* __restrict__ bsum, int nb) {
    if (threadIdx.x == 0) {
        int run = 0;
        for (int b = 0; b < nb; b++) { int t = bsum[b]; bsum[b] = run; run += t; }
    }
}
__global__ void scan3(int* __restrict__ rowptr, const int* __restrict__ bsum,
                      int* __restrict__ cursor, int N) {
    int i = blockIdx.x * blockDim.x + threadIdx.x;
    if (i == 0) {
        rowptr[0] = 0;
        cursor[0] = 0;
    } else if (i <= N) {
        int v = rowptr[i] + bsum[(i - 1) >> 9];
        rowptr[i] = v;
        if (i < N) cursor[i] = v;
    }
}
__global__ void fill_adj(const int* __restrict__ ei, int* __restrict__ cursor,
                         int* __restrict__ adj, int E) {
    int e = blockIdx.x * blockDim.x + threadIdx.x;
    if (e < E) adj[atomicAdd(&cursor[ei[E + e]], 1)] = ei[e];
}

// ---------------- gather: xa = x + sum_neigh x, output bf16 hi/lo ----------------
__global__ void gather_kernel(const float* __restrict__ x,
                              const int* __restrict__ rowptr,
                              const int* __restrict__ adj,
                              __nv_bfloat16* __restrict__ xah,
                              __nv_bfloat16* __restrict__ xal, int N) {
    int node = (blockIdx.x * blockDim.x + threadIdx.x) >> 5;
    int lane = threadIdx.x & 31;
    if (node >= N) return;
    float4 acc = *(const float4*)(x + (size_t)node * DD + lane * 4);
    int e = rowptr[node], end = rowptr[node + 1];
    for (; e + 1 < end; e += 2) {
        int s0 = adj[e], s1 = adj[e + 1];
        float4 v0 = *(const float4*)(x + (size_t)s0 * DD + lane * 4);
        float4 v1 = *(const float4*)(x + (size_t)s1 * DD + lane * 4);
        acc.x += v0.x + v1.x; acc.y += v0.y + v1.y;
        acc.z += v0.z + v1.z; acc.w += v0.w + v1.w;
    }
    if (e < end) {
        int s = adj[e];
        float4 v = *(const float4*)(x + (size_t)s * DD + lane * 4);
        acc.x += v.x; acc.y += v.y; acc.z += v.z; acc.w += v.w;
    }
    float hx = bfhi(acc.x), hy = bfhi(acc.y), hz = bfhi(acc.z), hw = bfhi(acc.w);
    size_t o = (size_t)node * DD + lane * 4;
    *(uint2*)(xah + o) = make_uint2(packbf(hx, hy), packbf(hz, hw));
    *(uint2*)(xal + o) =
        make_uint2(packbf(acc.x - hx, acc.y - hy), packbf(acc.z - hz, acc.w - hw));
}

// ---------------- split x (fp32 -> bf16 hi/lo) ----------------
__global__ void split_x(const float* __restrict__ x, __nv_bfloat16* __restrict__ xh,
                        __nv_bfloat16* __restrict__ xl, int total4) {
    int i = blockIdx.x * blockDim.x + threadIdx.x;
    if (i >= total4) return;
    float4 v = *(const float4*)(x + (size_t)i * 4);
    float hx = bfhi(v.x), hy = bfhi(v.y), hz = bfhi(v.z), hw = bfhi(v.w);
    *(uint2*)(xh + (size_t)i * 4) = make_uint2(packbf(hx, hy), packbf(hz, hw));
    *(uint2*)(xl + (size_t)i * 4) =
        make_uint2(packbf(v.x - hx, v.y - hy), packbf(v.z - hz, v.w - hw));
}

// ---------------- weight prep ----------------
__global__ void prep_weights(const float* __restrict__ w1, const float* __restrict__ w2,
                             const float* __restrict__ rw, const float* __restrict__ b2,
                             const float* __restrict__ rb,
                             __nv_bfloat16* __restrict__ wT1h, __nv_bfloat16* __restrict__ wT1l,
                             __nv_bfloat16* __restrict__ wTch, __nv_bfloat16* __restrict__ wTcl,
                             float* __restrict__ bc) {
    int idx = blockIdx.x * blockDim.x + threadIdx.x;
    if (idx < 3 * DD * DD) {
        int l = idx / (DD * DD), r = idx % (DD * DD), n = r / DD, k = r % DD;
        float v = w1[l * DD * DD + k * DD + n];
        float hi = bfhi(v);
        wT1h[idx] = __float2bfloat16_rn(v);
        wT1l[idx] = __float2bfloat16_rn(v - hi);
    }
    int i2 = idx - 3 * DD * DD;
    if (i2 >= 0 && i2 < 3 * DD * 256) {
        int l = i2 / (DD * 256), r = i2 % (DD * 256), n = r / 256, k2 = r % 256;
        float v = (k2 < DD) ? w2[l * DD * DD + k2 * DD + n]
                            : rw[l * DD * DD + (k2 - DD) * DD + n];
        float hi = bfhi(v);
        wTch[i2] = __float2bfloat16_rn(v);
        wTcl[i2] = __float2bfloat16_rn(v - hi);
    }
    if (idx < 3 * DD) bc[idx] = b2[idx] + rb[idx];
}

// ---------------- persistent bf16x3 GEMM — all operands cp.async from split arrays ----
// CAT=false: out = relu(A @ W^T + bias)  A=[N,128] hi/lo, out -> split only (h)
// CAT=true : out = [A | A2] @ W^T + bias A,A2=[N,128] hi/lo; out -> fp32 (+split opt)
// smem: A (hi@0, lo@18432) + B (hi@36864, lo@55296) = 73728 -> 2 CTA/SM.
#define TROW 72
#define O_A 0u
#define HLO 18432u
#define O_B 36864u
#define SM_TOTAL 73728

template <bool CAT>
__global__ __launch_bounds__(256, 2) void gemm_bf16(
    const __nv_bfloat16* __restrict__ Ah, const __nv_bfloat16* __restrict__ Al,
    const __nv_bfloat16* __restrict__ A2h, const __nv_bfloat16* __restrict__ A2l,
    const __nv_bfloat16* __restrict__ Bhi, const __nv_bfloat16* __restrict__ Blo,
    const float* __restrict__ bias,
    float* __restrict__ C, __nv_bfloat16* __restrict__ Chi,
    __nv_bfloat16* __restrict__ Clo,
    int M, int relu, int write_f32, int write_split) {
    extern __shared__ char smem[];
    const uint32_t sb = smem_u32(smem);
    const int tid = threadIdx.x, wid = tid >> 5, lane = tid & 31;
    const int wm = wid & 3, wn = wid >> 2;
    const int BK = CAT ? 256 : 128;
    const int NC = CAT ? 4 : 2;
    const int tiles = (M + 127) / 128;

    const uint32_t aBase = (uint32_t)((wm * 32 + (lane & 15)) * TROW + (lane >> 4) * 8) * 2;
    const uint32_t bBase = (uint32_t)((wn * 64 + (lane & 7) + ((lane >> 4) & 1) * 8) * TROW +
                                      ((lane >> 3) & 1) * 8) * 2;

    for (int t = blockIdx.x; t < tiles; t += gridDim.x) {
        const int m0 = t * 128;
        float acc[2][8][4];
#pragma unroll
        for (int mi = 0; mi < 2; mi++)
#pragma unroll
            for (int ni = 0; ni < 8; ni++)
#pragma unroll
                for (int q = 0; q < 4; q++) acc[mi][ni][q] = 0.f;

        for (int c = 0; c < NC; c++) {
            // ---- fill A chunk c (cp.async from split arrays) ----
            const __nv_bfloat16* Asel_h = (CAT && c >= 2) ? A2h : Ah;
            const __nv_bfloat16* Asel_l = (CAT && c >= 2) ? A2l : Al;
            const int ak0 = CAT ? ((c & 1) * 64) : (c * 64);
#pragma unroll
            for (int it = 0; it < 4; it++) {
                int i = tid + it * 256;
                int row = i >> 3, s = i & 7;
                int m = m0 + row;
                int full = (m < M) ? 16 : 0;
                int mc = (m < M) ? m : 0;  // clamp address, zero-fill via src-size
                size_t gl = (size_t)mc * DD + ak0 + s * 8;
                uint32_t off = (uint32_t)(row * TROW * 2 + s * 16);
                cp16z(sb + O_A + off, Asel_h + gl, full);
                cp16z(sb + O_A + HLO + off, Asel_l + gl, full);
            }
            // ---- fill B chunk c ----
            const int bk0 = c * 64;
#pragma unroll
            for (int it = 0; it < 4; it++) {
                int i = tid + it * 256;
                int row = i >> 3, s = i & 7;
                uint32_t off = (uint32_t)(row * TROW * 2 + s * 16);
                cp16(sb + O_B + off, Bhi + (size_t)row * BK + bk0 + s * 8);
                cp16(sb + O_B + HLO + off, Blo + (size_t)row * BK + bk0 + s * 8);
            }
            CP_COMMIT();
            CP_WAIT0();
            __syncthreads();

            // ---- compute chunk c ----
#pragma unroll
            for (int ks = 0; ks < 4; ks++) {
                uint32_t ah[2][4], al[2][4];
#pragma unroll
                for (int mi = 0; mi < 2; mi++) {
                    uint32_t ao = O_A + aBase + (uint32_t)(mi * 16 * TROW * 2 + ks * 32);
                    ldm4(ah[mi][0], ah[mi][1], ah[mi][2], ah[mi][3], sb + ao);
                    ldm4(al[mi][0], al[mi][1], al[mi][2], al[mi][3], sb + ao + HLO);
                }
                uint32_t bh[8][2], bl[8][2];
#pragma unroll
                for (int np = 0; np < 4; np++) {
                    uint32_t bo = O_B + bBase + (uint32_t)(np * 16 * TROW * 2 + ks * 32);
                    ldm4(bh[2 * np][0], bh[2 * np][1], bh[2 * np + 1][0], bh[2 * np + 1][1],
                         sb + bo);
                    ldm4(bl[2 * np][0], bl[2 * np][1], bl[2 * np + 1][0], bl[2 * np + 1][1],
                         sb + bo + HLO);
                }
#pragma unroll
                for (int mi = 0; mi < 2; mi++)
#pragma unroll
                    for (int ni = 0; ni < 8; ni++) {
                        mma16816(acc[mi][ni], ah[mi], bh[ni]);
                        mma16816(acc[mi][ni], ah[mi], bl[ni]);
                        mma16816(acc[mi][ni], al[mi], bh[ni]);
                    }
            }
            __syncthreads();
        }

        // ---- epilogue ----
        const int tq = lane >> 2, tr = lane & 3;
#pragma unroll
        for (int mi = 0; mi < 2; mi++) {
            int r0 = m0 + wm * 32 + mi * 16 + tq;
            int r1 = r0 + 8;
#pragma unroll
            for (int ni = 0; ni < 8; ni++) {
                int col = wn * 64 + ni * 8 + tr * 2;
                float b0 = bias[col], b1 = bias[col + 1];
                float2 v0 = make_float2(acc[mi][ni][0] + b0, acc[mi][ni][1] + b1);
                float2 v1 = make_float2(acc[mi][ni][2] + b0, acc[mi][ni][3] + b1);
                if (relu) {
                    v0.x = fmaxf(v0.x, 0.f); v0.y = fmaxf(v0.y, 0.f);
                    v1.x = fmaxf(v1.x, 0.f); v1.y = fmaxf(v1.y, 0.f);
                }
                if (r0 < M) {
                    size_t o = (size_t)r0 * DD + col;
                    if (write_f32) *(float2*)(C + o) = v0;
                    if (write_split) {
                        float h0 = bfhi(v0.x), h1 = bfhi(v0.y);
                        *(uint32_t*)(Chi + o) = packbf(h0, h1);
                        *(uint32_t*)(Clo + o) = packbf(v0.x - h0, v0.y - h1);
                    }
                }
                if (r1 < M) {
                    size_t o = (size_t)r1 * DD + col;
                    if (write_f32) *(float2*)(C + o) = v1;
                    if (write_split) {
                        float h0 = bfhi(v1.x), h1 = bfhi(v1.y);
                        *(uint32_t*)(Chi + o) = packbf(h0, h1);
                        *(uint32_t*)(Clo + o) = packbf(v1.x - h0, v1.y - h1);
                    }
                }
            }
        }
        __syncthreads();  // smem reused by next tile
    }
}

// ---------------- pooling ----------------
__global__ void pool_accum(const float* __restrict__ x,
                           const int* __restrict__ batch,
                           float* __restrict__ sums, float* __restrict__ counts,
                           int N) {
    int d = threadIdx.x;
    int per = (N + gridDim.x - 1) / gridDim.x;
    int n0 = blockIdx.x * per;
    int n1 = min(N, n0 + per);
    if (n0 >= n1) return;
    int cur = batch[n0];
    float acc = 0.f;
    int cnt = 0;
    for (int n = n0; n < n1; n++) {
        int g = batch[n];
        if (g != cur) {
            atomicAdd(&sums[cur * DD + d], acc);
            if (d == 0) atomicAdd(&counts[cur], (float)cnt);
            acc = 0.f; cnt = 0; cur = g;
        }
        acc += x[(size_t)n * DD + d];
        cnt++;
    }
    atomicAdd(&sums[cur * DD + d], acc);
    if (d == 0) atomicAdd(&counts[cur], (float)cnt);
}

__global__ void final_out(const float* __restrict__ sums,
                          const float* __restrict__ counts,
                          const float* __restrict__ out_w,
                          const float* __restrict__ out_b,
                          float* __restrict__ out) {
    int g = blockIdx.x;
    int d = threadIdx.x;
    float c = fmaxf(counts[g], 1.f);
    float v = (sums[g * DD + d] / c) * out_w[d];
    __shared__ float red[4];
#pragma unroll
    for (int o = 16; o; o >>= 1) v += __shfl_down_sync(0xFFFFFFFFu, v, o);
    if ((d & 31) == 0) red[d >> 5] = v;
    __syncthreads();
    if (d == 0) out[g] = red[0] + red[1] + red[2] + red[3] + out_b[0];
}

// ---------------- launch ----------------
extern "C" void kernel_launch(void* const* d_in, const int* in_sizes, int n_in,
                              void* d_out, int out_size) {
    const float* x_in = (const float*)d_in[0];
    const int* ei = (const int*)d_in[1];
    const int* batch = (const int*)d_in[2];
    const float* w1 = (const float*)d_in[3];
    const float* b1 = (const float*)d_in[4];
    const float* w2 = (const float*)d_in[5];
    const float* b2 = (const float*)d_in[6];
    const float* rw = (const float*)d_in[7];
    const float* rb = (const float*)d_in[8];
    const float* ow = (const float*)d_in[9];
    const float* ob = (const float*)d_in[10];
    float* out = (float*)d_out;

    int N = in_sizes[0] / DD;   // 50000
    int E = in_sizes[1] / 2;    // 600000
    int G = out_size;           // 64

    float *x1, *x2, *sums, *counts, *bc;
    __nv_bfloat16 *xah, *xal, *hh, *hl, *xsAh, *xsAl, *xsBh, *xsBl;
    __nv_bfloat16 *wT1h, *wT1l, *wTch, *wTcl;
    int *deg, *rowptr, *cursor, *adj, *bsum;
    cudaGetSymbolAddress((void**)&x1, g_x1);
    cudaGetSymbolAddress((void**)&x2, g_x2);
    cudaGetSymbolAddress((void**)&xah, g_xa_h);
    cudaGetSymbolAddress((void**)&xal, g_xa_l);
    cudaGetSymbolAddress((void**)&hh, g_h_h);
    cudaGetSymbolAddress((void**)&hl, g_h_l);
    cudaGetSymbolAddress((void**)&xsAh, g_xsA_h);
    cudaGetSymbolAddress((void**)&xsAl, g_xsA_l);
    cudaGetSymbolAddress((void**)&xsBh, g_xsB_h);
    cudaGetSymbolAddress((void**)&xsBl, g_xsB_l);
    cudaGetSymbolAddress((void**)&sums, g_sums);
    cudaGetSymbolAddress((void**)&counts, g_counts);
    cudaGetSymbolAddress((void**)&wT1h, g_wT1_hi);
    cudaGetSymbolAddress((void**)&wT1l, g_wT1_lo);
    cudaGetSymbolAddress((void**)&wTch, g_wTc_hi);
    cudaGetSymbolAddress((void**)&wTcl, g_wTc_lo);
    cudaGetSymbolAddress((void**)&bc, g_bc);
    cudaGetSymbolAddress((void**)&deg, g_deg);
    cudaGetSymbolAddress((void**)&rowptr, g_rowptr);
    cudaGetSymbolAddress((void**)&cursor, g_cursor);
    cudaGetSymbolAddress((void**)&adj, g_adj);
    cudaGetSymbolAddress((void**)&bsum, g_bsum);

    cudaFuncSetAttribute(gemm_bf16<false>, cudaFuncAttributeMaxDynamicSharedMemorySize, SM_TOTAL);
    cudaFuncSetAttribute(gemm_bf16<true>, cudaFuncAttributeMaxDynamicSharedMemorySize, SM_TOTAL);

    int nb = (N + 511) / 512;
    const int GRID = 296;  // 2 CTAs per SM

    // ---- CSR build ----
    cudaMemsetAsync(deg, 0, (size_t)N * sizeof(int), 0);
    deg_kernel<<<(E + 255) / 256, 256>>>(ei, deg, E);
    scan1<<<nb, 512>>>(deg, rowptr, bsum, N);
    scan2<<<1, 32>>>(bsum, nb);
    scan3<<<(N + 256) / 256, 256>>>(rowptr, bsum, cursor, N);
    fill_adj<<<(E + 255) / 256, 256>>>(ei, cursor, adj, E);

    prep_weights<<<(3 * DD * DD + 3 * DD * 256 + 255) / 256, 256>>>(
        w1, w2, rw, b2, rb, wT1h, wT1l, wTch, wTcl, bc);
    split_x<<<(N * DD / 4 + 255) / 256, 256>>>(x_in, xsAh, xsAl, N * DD / 4);

    int gather_blocks = (N * 32 + 255) / 256;
    const float* xp = x_in;
    float* xo[3] = {x1, x2, x1};
    for (int i = 0; i < 3; i++) {
        __nv_bfloat16* sc_h = (i & 1) ? xsBh : xsAh;   // split of current input
        __nv_bfloat16* sc_l = (i & 1) ? xsBl : xsAl;
        __nv_bfloat16* sn_h = (i & 1) ? xsAh : xsBh;   // split of output (next input)
        __nv_bfloat16* sn_l = (i & 1) ? xsAl : xsBl;
        gather_kernel<<<gather_blocks, 256>>>(xp, rowptr, adj, xah, xal, N);
        // h = relu(xa @ W1^T + b1) -> split only
        gemm_bf16<false><<<GRID, 256, SM_TOTAL>>>(
            xah, xal, nullptr, nullptr,
            wT1h + (size_t)i * DD * DD, wT1l + (size_t)i * DD * DD,
            b1 + i * DD, nullptr, hh, hl, N, 1, 0, 1);
        // xb = [h | x] @ Wc^T + bc -> fp32 (+ split if another layer follows)
        gemm_bf16<true><<<GRID, 256, SM_TOTAL>>>(
            hh, hl, sc_h, sc_l,
            wTch + (size_t)i * DD * 256, wTcl + (size_t)i * DD * 256,
            bc + i * DD, xo[i], sn_h, sn_l, N, (i < 2) ? 1 : 0, 1, (i < 2) ? 1 : 0);
        xp = xo[i];
    }

    cudaMemsetAsync(sums, 0, (size_t)G * DD * sizeof(float), 0);
    cudaMemsetAsync(counts, 0, (size_t)G * sizeof(float), 0);
    pool_accum<<<256, DD>>>(xp, batch, sums, counts, N);
    final_out<<<G, DD>>>(sums, counts, ow, ob, out);
}

// round 15
// speedup vs baseline: 1.1503x; 1.1503x over previous
#include <cuda_runtime.h>
#include <cuda_bf16.h>
#include <cstdint>

#define DD 128
#define NMAX 50000
#define EMAX 600000
#define GMAX 64

// ---------------- scratch (no allocations allowed) ----------------
__device__ float g_agg[NMAX * DD];
__device__ float g_h[NMAX * DD];
__device__ float g_x[NMAX * DD];
__device__ float g_pool[GMAX * DD + GMAX];   // sums then counts (one memset)
__device__ __nv_bfloat16 g_wT1_hi[3 * DD * DD];
__device__ __nv_bfloat16 g_wT1_lo[3 * DD * DD];
__device__ __nv_bfloat16 g_wTc_hi[3 * DD * 256];
__device__ __nv_bfloat16 g_wTc_lo[3 * DD * 256];
__device__ float g_bc[3 * DD];
__device__ int g_deg[NMAX];
__device__ int g_rowptr[NMAX + 1];
__device__ int g_cursor[NMAX];
__device__ int g_adj[EMAX];
__device__ int g_bsum[128];

// ---------------- helpers ----------------
__device__ __forceinline__ uint32_t smem_u32(const void* p) {
    uint32_t a;
    asm("{ .reg .u64 t; cvta.to.shared.u64 t, %1; cvt.u32.u64 %0, t; }"
        : "=r"(a) : "l"(p));
    return a;
}
__device__ __forceinline__ uint32_t packbf(float a, float b) {
    __nv_bfloat162 t = __floats2bfloat162_rn(a, b);
    return *reinterpret_cast<uint32_t*>(&t);
}
__device__ __forceinline__ void ldm4(uint32_t& r0, uint32_t& r1, uint32_t& r2,
                                     uint32_t& r3, uint32_t addr) {
    asm volatile("ldmatrix.sync.aligned.m8n8.x4.shared.b16 {%0,%1,%2,%3}, [%4];"
                 : "=r"(r0), "=r"(r1), "=r"(r2), "=r"(r3) : "r"(addr));
}
__device__ __forceinline__ void mma16816(float* c, const uint32_t* a, const uint32_t* b) {
    asm volatile(
        "mma.sync.aligned.m16n8k16.row.col.f32.bf16.bf16.f32 "
        "{%0,%1,%2,%3}, {%4,%5,%6,%7}, {%8,%9}, {%0,%1,%2,%3};"
        : "+f"(c[0]), "+f"(c[1]), "+f"(c[2]), "+f"(c[3])
        : "r"(a[0]), "r"(a[1]), "r"(a[2]), "r"(a[3]), "r"(b[0]), "r"(b[1]));
}
__device__ __forceinline__ void cp16(uint32_t saddr, const void* g) {
    asm volatile("cp.async.ca.shared.global [%0], [%1], 16;" :: "r"(saddr), "l"(g));
}
#define CP_COMMIT() asm volatile("cp.async.commit_group;" ::: "memory")
#define CP_WAIT0() asm volatile("cp.async.wait_group 0;" ::: "memory")

// ---------------- CSR build ----------------
__global__ void deg_kernel(const int* __restrict__ ei, int* __restrict__ deg, int E) {
    int e = blockIdx.x * blockDim.x + threadIdx.x;
    if (e < E) atomicAdd(&deg[ei[E + e]], 1);
}
__global__ void scan1(const int* __restrict__ deg, int* __restrict__ rowptr,
                      int* __restrict__ bsum, int N) {
    __shared__ int ws[16];
    int i = blockIdx.x * 512 + threadIdx.x;
    int lane = threadIdx.x & 31, w = threadIdx.x >> 5;
    int v = (i < N) ? deg[i] : 0;
#pragma unroll
    for (int o = 1; o < 32; o <<= 1) {
        int t = __shfl_up_sync(0xFFFFFFFFu, v, o);
        if (lane >= o) v += t;
    }
    if (lane == 31) ws[w] = v;
    __syncthreads();
    if (w == 0) {
        int s = (lane < 16) ? ws[lane] : 0;
#pragma unroll
        for (int o = 1; o < 16; o <<= 1) {
            int t = __shfl_up_sync(0xFFFFFFFFu, s, o);
            if (lane >= o) s += t;
        }
        if (lane < 16) ws[lane] = s;
    }
    __syncthreads();
    if (w > 0) v += ws[w - 1];
    if (i < N) rowptr[i + 1] = v;
    if (threadIdx.x == 511) bsum[blockIdx.x] = v;
}
__global__ void scan2(int* __restrict__ bsum, int nb) {
    if (threadIdx.x == 0) {
        int run = 0;
        for (int b = 0; b < nb; b++) { int t = bsum[b]; bsum[b] = run; run += t; }
    }
}
// finalizes rowptr AND writes cursor (merged)
__global__ void scan3(int* __restrict__ rowptr, const int* __restrict__ bsum,
                      int* __restrict__ cursor, int N) {
    int i = blockIdx.x * blockDim.x + threadIdx.x;
    if (i == 0) {
        rowptr[0] = 0;
        cursor[0] = 0;
    } else if (i <= N) {
        int v = rowptr[i] + bsum[(i - 1) >> 9];
        rowptr[i] = v;
        if (i < N) cursor[i] = v;
    }
}
__global__ void fill_adj(const int* __restrict__ ei, int* __restrict__ cursor,
                         int* __restrict__ adj, int E) {
    int e = blockIdx.x * blockDim.x + threadIdx.x;
    if (e < E) adj[atomicAdd(&cursor[ei[E + e]], 1)] = ei[e];
}

// ---------------- gather: xa[i] = x[i] + sum_{j in N(i)} x[j] ----------------
__global__ void gather_kernel(const float* __restrict__ x,
                              const int* __restrict__ rowptr,
                              const int* __restrict__ adj,
                              float* __restrict__ xa, int N) {
    int node = (blockIdx.x * blockDim.x + threadIdx.x) >> 5;
    int lane = threadIdx.x & 31;
    if (node >= N) return;
    float4 acc = *(const float4*)(x + (size_t)node * DD + lane * 4);
    int e = rowptr[node], end = rowptr[node + 1];
    for (; e + 1 < end; e += 2) {
        int s0 = adj[e], s1 = adj[e + 1];
        float4 v0 = *(const float4*)(x + (size_t)s0 * DD + lane * 4);
        float4 v1 = *(const float4*)(x + (size_t)s1 * DD + lane * 4);
        acc.x += v0.x + v1.x; acc.y += v0.y + v1.y;
        acc.z += v0.z + v1.z; acc.w += v0.w + v1.w;
    }
    if (e < end) {
        int s = adj[e];
        float4 v = *(const float4*)(x + (size_t)s * DD + lane * 4);
        acc.x += v.x; acc.y += v.y; acc.z += v.z; acc.w += v.w;
    }
    *(float4*)(xa + (size_t)node * DD + lane * 4) = acc;
}

// ---------------- weight prep ----------------
__global__ void prep_weights(const float* __restrict__ w1, const float* __restrict__ w2,
                             const float* __restrict__ rw, const float* __restrict__ b2,
                             const float* __restrict__ rb,
                             __nv_bfloat16* __restrict__ wT1h, __nv_bfloat16* __restrict__ wT1l,
                             __nv_bfloat16* __restrict__ wTch, __nv_bfloat16* __restrict__ wTcl,
                             float* __restrict__ bc) {
    int idx = blockIdx.x * blockDim.x + threadIdx.x;
    if (idx < 3 * DD * DD) {
        int l = idx / (DD * DD), r = idx % (DD * DD), n = r / DD, k = r % DD;
        float v = w1[l * DD * DD + k * DD + n];
        __nv_bfloat16 hi = __float2bfloat16_rn(v);
        wT1h[idx] = hi;
        wT1l[idx] = __float2bfloat16_rn(v - __bfloat162float(hi));
    }
    int i2 = idx - 3 * DD * DD;
    if (i2 >= 0 && i2 < 3 * DD * 256) {
        int l = i2 / (DD * 256), r = i2 % (DD * 256), n = r / 256, k2 = r % 256;
        float v = (k2 < DD) ? w2[l * DD * DD + k2 * DD + n]
                            : rw[l * DD * DD + (k2 - DD) * DD + n];
        __nv_bfloat16 hi = __float2bfloat16_rn(v);
        wTch[i2] = hi;
        wTcl[i2] = __float2bfloat16_rn(v - __bfloat162float(hi));
    }
    if (idx < 3 * DD) bc[idx] = b2[idx] + rb[idx];
}

// ---------------- persistent bf16x3 GEMM, 2 CTAs/SM, single-buffered (R11) --------
// CAT=false: C = relu_if(A @ W^T + bias)          W^T: [128n x 128k]
// CAT=true : C = relu_if([A | A2] @ W^T + bias)   W^T: [128n x 256k]
#define TROW 72
#define O_AH 0u
#define O_AL 18432u
#define O_BH 36864u
#define O_BL 55296u
#define SM_TOTAL 73728

template <bool CAT>
__global__ __launch_bounds__(256, 2) void gemm_bf16(
    const float* __restrict__ A, const float* __restrict__ A2,
    const __nv_bfloat16* __restrict__ Bhi, const __nv_bfloat16* __restrict__ Blo,
    const float* __restrict__ bias, float* __restrict__ C, int M, int relu) {
    extern __shared__ char smem[];
    const uint32_t sb = smem_u32(smem);
    const int tid = threadIdx.x, wid = tid >> 5, lane = tid & 31;
    const int wm = wid & 3, wn = wid >> 2;
    const int BK = CAT ? 256 : 128;
    const int NC = CAT ? 4 : 2;
    const int tiles = (M + 127) / 128;

    const uint32_t aBase = (uint32_t)((wm * 32 + (lane & 15)) * TROW + (lane >> 4) * 8) * 2;
    const uint32_t bBase = (uint32_t)((wn * 64 + (lane & 7) + ((lane >> 4) & 1) * 8) * TROW +
                                      ((lane >> 3) & 1) * 8) * 2;

    for (int t = blockIdx.x; t < tiles; t += gridDim.x) {
        const int m0 = t * 128;
        float acc[2][8][4];
#pragma unroll
        for (int mi = 0; mi < 2; mi++)
#pragma unroll
            for (int ni = 0; ni < 8; ni++)
#pragma unroll
                for (int q = 0; q < 4; q++) acc[mi][ni][q] = 0.f;

        for (int c = 0; c < NC; c++) {
            // ---- fill B chunk c via cp.async ----
            const int bk0 = c * 64;
#pragma unroll
            for (int it = 0; it < 4; it++) {
                int i = tid + it * 256;
                int row = i >> 3, s = i & 7;
                uint32_t off = (uint32_t)(row * TROW * 2 + s * 16);
                cp16(sb + O_BH + off, Bhi + (size_t)row * BK + bk0 + s * 8);
                cp16(sb + O_BL + off, Blo + (size_t)row * BK + bk0 + s * 8);
            }
            CP_COMMIT();
            // ---- fill A chunk c (LDG + bf16 split) ----
            const float* Asrc = CAT ? ((c < 2) ? A : A2) : A;
            const int ak0 = CAT ? ((c & 1) * 64) : (c * 64);
#pragma unroll
            for (int it = 0; it < 8; it++) {
                int i = tid + it * 256;
                int row = i >> 4, s = i & 15;
                int m = m0 + row;
                float4 v = (m < M) ? *(const float4*)(Asrc + (size_t)m * DD + ak0 + s * 4)
                                   : make_float4(0.f, 0.f, 0.f, 0.f);
                float hx = __bfloat162float(__float2bfloat16_rn(v.x));
                float hy = __bfloat162float(__float2bfloat16_rn(v.y));
                float hz = __bfloat162float(__float2bfloat16_rn(v.z));
                float hw = __bfloat162float(__float2bfloat16_rn(v.w));
                uint32_t off = (uint32_t)(row * TROW * 2 + s * 8);
                *(uint2*)(smem + O_AH + off) = make_uint2(packbf(hx, hy), packbf(hz, hw));
                *(uint2*)(smem + O_AL + off) =
                    make_uint2(packbf(v.x - hx, v.y - hy), packbf(v.z - hz, v.w - hw));
            }
            CP_WAIT0();
            __syncthreads();

            // ---- compute chunk c ----
#pragma unroll
            for (int ks = 0; ks < 4; ks++) {
                uint32_t ah[2][4], al[2][4];
#pragma unroll
                for (int mi = 0; mi < 2; mi++) {
                    uint32_t ao = aBase + (uint32_t)(mi * 16 * TROW * 2 + ks * 32);
                    ldm4(ah[mi][0], ah[mi][1], ah[mi][2], ah[mi][3], sb + O_AH + ao);
                    ldm4(al[mi][0], al[mi][1], al[mi][2], al[mi][3], sb + O_AL + ao);
                }
                uint32_t bh[8][2], bl[8][2];
#pragma unroll
                for (int np = 0; np < 4; np++) {
                    uint32_t bo = bBase + (uint32_t)(np * 16 * TROW * 2 + ks * 32);
                    ldm4(bh[2 * np][0], bh[2 * np][1], bh[2 * np + 1][0], bh[2 * np + 1][1],
                         sb + O_BH + bo);
                    ldm4(bl[2 * np][0], bl[2 * np][1], bl[2 * np + 1][0], bl[2 * np + 1][1],
                         sb + O_BL + bo);
                }
#pragma unroll
                for (int mi = 0; mi < 2; mi++)
#pragma unroll
                    for (int ni = 0; ni < 8; ni++) {
                        mma16816(acc[mi][ni], ah[mi], bh[ni]);
                        mma16816(acc[mi][ni], ah[mi], bl[ni]);
                        mma16816(acc[mi][ni], al[mi], bh[ni]);
                    }
            }
            __syncthreads();
        }

        // ---- epilogue (registers only) ----
        const int tq = lane >> 2, tr = lane & 3;
#pragma unroll
        for (int mi = 0; mi < 2; mi++) {
            int r0 = m0 + wm * 32 + mi * 16 + tq;
            int r1 = r0 + 8;
#pragma unroll
            for (int ni = 0; ni < 8; ni++) {
                int col = wn * 64 + ni * 8 + tr * 2;
                float b0 = bias[col], b1 = bias[col + 1];
                float2 v0 = make_float2(acc[mi][ni][0] + b0, acc[mi][ni][1] + b1);
                float2 v1 = make_float2(acc[mi][ni][2] + b0, acc[mi][ni][3] + b1);
                if (relu) {
                    v0.x = fmaxf(v0.x, 0.f); v0.y = fmaxf(v0.y, 0.f);
                    v1.x = fmaxf(v1.x, 0.f); v1.y = fmaxf(v1.y, 0.f);
                }
                if (r0 < M) *(float2*)(C + (size_t)r0 * DD + col) = v0;
                if (r1 < M) *(float2*)(C + (size_t)r1 * DD + col) = v1;
            }
        }
    }
}

// ---------------- pooling ----------------
__global__ void pool_accum(const float* __restrict__ x,
                           const int* __restrict__ batch,
                           float* __restrict__ sums, float* __restrict__ counts,
                           int N) {
    int d = threadIdx.x;
    int per = (N + gridDim.x - 1) / gridDim.x;
    int n0 = blockIdx.x * per;
    int n1 = min(N, n0 + per);
    if (n0 >= n1) return;
    int cur = batch[n0];
    float acc = 0.f;
    int cnt = 0;
    for (int n = n0; n < n1; n++) {
        int g = batch[n];
        if (g != cur) {
            atomicAdd(&sums[cur * DD + d], acc);
            if (d == 0) atomicAdd(&counts[cur], (float)cnt);
            acc = 0.f; cnt = 0; cur = g;
        }
        acc += x[(size_t)n * DD + d];
        cnt++;
    }
    atomicAdd(&sums[cur * DD + d], acc);
    if (d == 0) atomicAdd(&counts[cur], (float)cnt);
}

__global__ void final_out(const float* __restrict__ sums,
                          const float* __restrict__ counts,
                          const float* __restrict__ out_w,
                          const float* __restrict__ out_b,
                          float* __restrict__ out) {
    int g = blockIdx.x;
    int d = threadIdx.x;
    float c = fmaxf(counts[g], 1.f);
    float v = (sums[g * DD + d] / c) * out_w[d];
    __shared__ float red[4];
#pragma unroll
    for (int o = 16; o; o >>= 1) v += __shfl_down_sync(0xFFFFFFFFu, v, o);
    if ((d & 31) == 0) red[d >> 5] = v;
    __syncthreads();
    if (d == 0) out[g] = red[0] + red[1] + red[2] + red[3] + out_b[0];
}

// ---------------- launch ----------------
extern "C" void kernel_launch(void* const* d_in, const int* in_sizes, int n_in,
                              void* d_out, int out_size) {
    const float* x_in = (const float*)d_in[0];
    const int* ei = (const int*)d_in[1];
    const int* batch = (const int*)d_in[2];
    const float* w1 = (const float*)d_in[3];
    const float* b1 = (const float*)d_in[4];
    const float* w2 = (const float*)d_in[5];
    const float* b2 = (const float*)d_in[6];
    const float* rw = (const float*)d_in[7];
    const float* rb = (const float*)d_in[8];
    const float* ow = (const float*)d_in[9];
    const float* ob = (const float*)d_in[10];
    float* out = (float*)d_out;

    int N = in_sizes[0] / DD;   // 50000
    int E = in_sizes[1] / 2;    // 600000
    int G = out_size;           // 64

    float *xa, *h, *xb, *pool, *bc;
    __nv_bfloat16 *wT1h, *wT1l, *wTch, *wTcl;
    int *deg, *rowptr, *cursor, *adj, *bsum;
    cudaGetSymbolAddress((void**)&xa, g_agg);
    cudaGetSymbolAddress((void**)&h, g_h);
    cudaGetSymbolAddress((void**)&xb, g_x);
    cudaGetSymbolAddress((void**)&pool, g_pool);
    cudaGetSymbolAddress((void**)&wT1h, g_wT1_hi);
    cudaGetSymbolAddress((void**)&wT1l, g_wT1_lo);
    cudaGetSymbolAddress((void**)&wTch, g_wTc_hi);
    cudaGetSymbolAddress((void**)&wTcl, g_wTc_lo);
    cudaGetSymbolAddress((void**)&bc, g_bc);
    cudaGetSymbolAddress((void**)&deg, g_deg);
    cudaGetSymbolAddress((void**)&rowptr, g_rowptr);
    cudaGetSymbolAddress((void**)&cursor, g_cursor);
    cudaGetSymbolAddress((void**)&adj, g_adj);
    cudaGetSymbolAddress((void**)&bsum, g_bsum);
    float* sums = pool;
    float* counts = pool + (size_t)G * DD;

    cudaFuncSetAttribute(gemm_bf16<false>, cudaFuncAttributeMaxDynamicSharedMemorySize, SM_TOTAL);
    cudaFuncSetAttribute(gemm_bf16<true>, cudaFuncAttributeMaxDynamicSharedMemorySize, SM_TOTAL);

    int nb = (N + 511) / 512;
    const int GRID = 296;  // 2 CTAs per SM

    // ---- CSR build ----
    cudaMemsetAsync(deg, 0, (size_t)N * sizeof(int), 0);
    deg_kernel<<<(E + 255) / 256, 256>>>(ei, deg, E);
    scan1<<<nb, 512>>>(deg, rowptr, bsum, N);
    scan2<<<1, 32>>>(bsum, nb);
    scan3<<<(N + 256) / 256, 256>>>(rowptr, bsum, cursor, N);
    fill_adj<<<(E + 255) / 256, 256>>>(ei, cursor, adj, E);

    prep_weights<<<(3 * DD * DD + 3 * DD * 256 + 255) / 256, 256>>>(
        w1, w2, rw, b2, rb, wT1h, wT1l, wTch, wTcl, bc);

    int gather_blocks = (N * 32 + 255) / 256;
    const float* xp = x_in;
    for (int i = 0; i < 3; i++) {
        gather_kernel<<<gather_blocks, 256>>>(xp, rowptr, adj, xa, N);
        gemm_bf16<false><<<GRID, 256, SM_TOTAL>>>(
            xa, nullptr, wT1h + (size_t)i * DD * DD, wT1l + (size_t)i * DD * DD,
            b1 + i * DD, h, N, 1);
        gemm_bf16<true><<<GRID, 256, SM_TOTAL>>>(
            h, xp, wTch + (size_t)i * DD * 256, wTcl + (size_t)i * DD * 256,
            bc + i * DD, xb, N, (i < 2) ? 1 : 0);
        xp = xb;
    }

    cudaMemsetAsync(pool, 0, ((size_t)G * DD + G) * sizeof(float), 0);
    pool_accum<<<256, DD>>>(xp, batch, sums, counts, N);
    final_out<<<G, DD>>>(sums, counts, ow, ob, out);
}